// round 9
// baseline (speedup 1.0000x reference)
#include <cuda_runtime.h>
#include <cuda_bf16.h>
#include <cstdint>

// out[n] = 0.1*Ax[n] - 0.1*deg[n]*x[n] + 0.9*(S[n] - cnt[n]*x[n]^2)
//
// Random-op-count architecture (op count is THE cost: ~147 random L2 ops/cyc chip-wide):
//   - x quantized once to u16 table g_xq (1MB)
//   - nodes [0, SMEM_NODES) additionally staged in 192KB smem per SM;
//     ~20% of gathers served by the smem crossbar instead of L1tex/LTS
//   - one packed 64-bit RED.ADD per edge slot:
//       bits [ 0:40) fixed-point sum (0.1*x[src] / 0.9*p), scale 2^30
//       bits [40:52) hyper slot count
//       bits [52:64) adjacency degree
//   - decode uses exact fp32 x for deg*x and cnt*x^2, and RE-ZEROS g_acc
//     (so no memset node is needed; __device__ globals start zeroed)

#define MAX_N      524288
#define SMEM_NODES 98304          // 96K nodes * u16 = 192KB smem
#define FX_SCALE   1073741824.0f  // 2^30
#define XQ_SCALE   65536.0f
#define EDGE_TPB   1024
#define EDGE_GRID  152

__device__ unsigned long long g_acc[MAX_N];   // zero-initialized at module load
__device__ unsigned short     g_xq[MAX_N];

__device__ __forceinline__ unsigned long long pack_hyper(float v) {
    return (1ULL << 40) | (unsigned long long)__float2uint_rn(v * FX_SCALE);
}
__device__ __forceinline__ unsigned long long pack_adj(float v) {
    return (1ULL << 52) | (unsigned long long)__float2uint_rn(v * FX_SCALE);
}

__global__ void quant_kernel(const float* __restrict__ x, int N)
{
    int n4 = blockIdx.x * blockDim.x + threadIdx.x;   // group of 4
    int base = n4 * 4;
    if (base + 3 < N) {
        float4 v = __ldcs((const float4*)(x + base));
        ushort4 q;
        q.x = (unsigned short)min(__float2uint_rn(v.x * XQ_SCALE), 65535u);
        q.y = (unsigned short)min(__float2uint_rn(v.y * XQ_SCALE), 65535u);
        q.z = (unsigned short)min(__float2uint_rn(v.z * XQ_SCALE), 65535u);
        q.w = (unsigned short)min(__float2uint_rn(v.w * XQ_SCALE), 65535u);
        *(ushort4*)(g_xq + base) = q;
    } else {
        for (int i = base; i < N; i++) {
            uint32_t u = __float2uint_rn(x[i] * XQ_SCALE);
            g_xq[i] = (unsigned short)min(u, 65535u);
        }
    }
}

extern __shared__ unsigned short s_x[];   // SMEM_NODES u16

// gather: smem shard for low indices, global u16 table otherwise
__device__ __forceinline__ float gx(int i)
{
    unsigned short v;
    if (i < SMEM_NODES) v = s_x[i];
    else                v = __ldg(&g_xq[i]);
    return (float)v * (1.0f / XQ_SCALE);
}

__global__ void __launch_bounds__(EDGE_TPB, 1)
edge_kernel(const int* __restrict__ he,  int nH,
            const int* __restrict__ adj, int nA)
{
    // stage smem shard from the u16 table (coalesced uint4 = 8 values/load)
    {
        const uint4* src = (const uint4*)g_xq;          // 8 u16 per uint4
        uint4*       dst = (uint4*)s_x;
        const int nVec = SMEM_NODES / 8;
        for (int i = threadIdx.x; i < nVec; i += EDGE_TPB)
            dst[i] = src[i];
    }
    __syncthreads();

    const int tid    = blockIdx.x * EDGE_TPB + threadIdx.x;
    const int stride = gridDim.x * EDGE_TPB;

    // ---- hyper edges: groups of 4 edges (12 ints = 3x streaming int4) ----
    {
        const int nGroups = nH >> 2;
        const int4* he4 = (const int4*)he;
        for (int g = tid; g < nGroups; g += stride) {
            int4 a = __ldcs(he4 + 3 * g + 0);
            int4 b = __ldcs(he4 + 3 * g + 1);
            int4 c = __ldcs(he4 + 3 * g + 2);
            int idx[12] = { a.x, a.y, a.z, a.w,
                            b.x, b.y, b.z, b.w,
                            c.x, c.y, c.z, c.w };
            float xv[8];
            #pragma unroll
            for (int e = 0; e < 4; e++) {
                xv[2 * e + 0] = gx(idx[3 * e + 1]);
                xv[2 * e + 1] = gx(idx[3 * e + 2]);
            }
            #pragma unroll
            for (int e = 0; e < 4; e++) {
                float p = 0.9f * xv[2 * e + 0] * xv[2 * e + 1];
                unsigned long long payload = pack_hyper(p);
                atomicAdd(&g_acc[idx[3 * e + 0]], payload);
                atomicAdd(&g_acc[idx[3 * e + 1]], payload);
                atomicAdd(&g_acc[idx[3 * e + 2]], payload);
            }
        }
        // scalar tail (nH % 4): handled once by low global tids
        int tailStart = nGroups << 2;
        int t = tailStart + tid;
        if (t < nH) {
            int i0 = he[3 * t + 0];
            int i1 = he[3 * t + 1];
            int i2 = he[3 * t + 2];
            float p = 0.9f * gx(i1) * gx(i2);
            unsigned long long payload = pack_hyper(p);
            atomicAdd(&g_acc[i0], payload);
            atomicAdd(&g_acc[i1], payload);
            atomicAdd(&g_acc[i2], payload);
        }
    }

    // ---- adjacency edges: groups of 4 edges (2x streaming int4) ----
    {
        const int nGroups = nA >> 2;
        const int4* adj4 = (const int4*)adj;
        for (int g = tid; g < nGroups; g += stride) {
            int4 e0 = __ldcs(adj4 + 2 * g + 0);  // (s0,d0,s1,d1)
            int4 e1 = __ldcs(adj4 + 2 * g + 1);  // (s2,d2,s3,d3)
            float s0 = gx(e0.x);
            float s1 = gx(e0.z);
            float s2 = gx(e1.x);
            float s3 = gx(e1.z);
            atomicAdd(&g_acc[e0.y], pack_adj(0.1f * s0));
            atomicAdd(&g_acc[e0.w], pack_adj(0.1f * s1));
            atomicAdd(&g_acc[e1.y], pack_adj(0.1f * s2));
            atomicAdd(&g_acc[e1.w], pack_adj(0.1f * s3));
        }
        int tailStart = nGroups << 2;
        int t = tailStart + tid;
        if (t < nA) {
            int s = adj[2 * t + 0];
            int d = adj[2 * t + 1];
            atomicAdd(&g_acc[d], pack_adj(0.1f * gx(s)));
        }
    }
}

__global__ void decode_kernel(const float* __restrict__ x,
                              float*       __restrict__ out,
                              int N)
{
    int n2 = blockIdx.x * blockDim.x + threadIdx.x;   // pair of nodes
    int base = n2 * 2;
    if (base >= N) return;

    ulonglong2 av = *(ulonglong2*)(g_acc + base);
    // re-zero for the next replay (keeps module-load-zero invariant)
    ulonglong2 z; z.x = 0ULL; z.y = 0ULL;
    *(ulonglong2*)(g_acc + base) = z;

    float2 xv2 = *(const float2*)(x + base);
    float r[2];
    unsigned long long aa[2] = { av.x, av.y };
    float xs[2] = { xv2.x, xv2.y };
    #pragma unroll
    for (int k = 0; k < 2; k++) {
        unsigned long long a = aa[k];
        double sum = (double)(a & ((1ULL << 40) - 1)) * (1.0 / (double)FX_SCALE);
        int cntH = (int)((a >> 40) & 0xFFF);
        int degA = (int)((a >> 52) & 0xFFF);
        float xv = xs[k];
        r[k] = (float)sum - 0.1f * (float)degA * xv - 0.9f * (float)cntH * xv * xv;
    }
    if (base + 1 < N) {
        *(float2*)(out + base) = make_float2(r[0], r[1]);
    } else {
        out[base] = r[0];
    }
}

extern "C" void kernel_launch(void* const* d_in, const int* in_sizes, int n_in,
                              void* d_out, int out_size)
{
    const float* x   = (const float*)d_in[0];
    const int*   he  = (const int*)d_in[2];
    const int*   adj = (const int*)d_in[3];
    float*       out = (float*)d_out;

    const int nH = in_sizes[2] / 3;
    const int nA = in_sizes[3] / 2;
    const int N  = out_size;

    // 192KB dynamic smem for the edge kernel
    cudaFuncSetAttribute(edge_kernel,
                         cudaFuncAttributeMaxDynamicSharedMemorySize,
                         SMEM_NODES * (int)sizeof(unsigned short));

    const int threads = 256;

    // build u16 x table (1MB)
    int qBlocks = ((N + 3) / 4 + threads - 1) / threads;
    quant_kernel<<<qBlocks, threads>>>(x, N);

    // persistent edge kernel: 1 CTA/SM, smem shard + grid-stride over all edges
    edge_kernel<<<EDGE_GRID, EDGE_TPB, SMEM_NODES * sizeof(unsigned short)>>>(
        he, nH, adj, nA);

    // decode + re-zero accumulators (no memset node needed)
    int decBlocks = ((N + 1) / 2 + threads - 1) / threads;
    decode_kernel<<<decBlocks, threads>>>(x, out, N);
}

// round 10
// speedup vs baseline: 1.0794x; 1.0794x over previous
#include <cuda_runtime.h>
#include <cuda_bf16.h>
#include <cstdint>

// out[n] = 0.1*Ax[n] - 0.1*deg[n]*x[n] + 0.9*(S[n] - cnt[n]*x[n]^2)
//
// Bound: per-SM L1tex wavefront issue (~1/cyc/SM). Wavefront count is
// algebraically minimal: hyper edge = 2 gathers + 3 REDs, adj edge = 1 gather
// + 1 RED  (57M total). This round removes all fixed overhead around that.
//
// Per-node 64-bit packed accumulator, one RED.E.ADD.U64 per edge slot:
//   bits [ 0:40) fixed-point sum of (0.1*x[src]) and (0.9*p), scale 2^30
//   bits [40:52) hyper slot count
//   bits [52:64) adjacency degree
// Decode subtracts 0.1*deg*x + 0.9*cnt*x^2 using exact fp32 x, then re-zeros
// g_acc so no memset node is needed (globals start zeroed at module load).

#define MAX_N    524288
#define FX_SCALE 1073741824.0f   // 2^30

__device__ unsigned long long g_acc[MAX_N];   // zero-initialized at load

__device__ __forceinline__ unsigned long long pack_hyper(float v) {
    return (1ULL << 40) | (unsigned long long)__float2uint_rn(v * FX_SCALE);
}
__device__ __forceinline__ unsigned long long pack_adj(float v) {
    return (1ULL << 52) | (unsigned long long)__float2uint_rn(v * FX_SCALE);
}

__global__ void edge_kernel(const float* __restrict__ x,
                            const int*   __restrict__ he,   // [nH*3]
                            int nH,
                            const int*   __restrict__ adj,  // [nA*2]
                            int nA,
                            int hyperBlocks)
{
    if ((int)blockIdx.x < hyperBlocks) {
        // ---- hyper edges: 4 edges (12 ints) per thread via 3x streaming int4 ----
        const int g = blockIdx.x * blockDim.x + threadIdx.x;
        const int nGroups = nH >> 2;

        if (g < nGroups) {
            const int4* he4 = (const int4*)he;
            int4 a = __ldcs(he4 + 3 * g + 0);
            int4 b = __ldcs(he4 + 3 * g + 1);
            int4 c = __ldcs(he4 + 3 * g + 2);
            int idx[12] = { a.x, a.y, a.z, a.w,
                            b.x, b.y, b.z, b.w,
                            c.x, c.y, c.z, c.w };
            // batch all 8 gathers first (MLP)
            float xv[8];
            #pragma unroll
            for (int e = 0; e < 4; e++) {
                xv[2 * e + 0] = __ldg(x + idx[3 * e + 1]);
                xv[2 * e + 1] = __ldg(x + idx[3 * e + 2]);
            }
            #pragma unroll
            for (int e = 0; e < 4; e++) {
                float p = 0.9f * xv[2 * e + 0] * xv[2 * e + 1];
                unsigned long long payload = pack_hyper(p);
                atomicAdd(&g_acc[idx[3 * e + 0]], payload);
                atomicAdd(&g_acc[idx[3 * e + 1]], payload);
                atomicAdd(&g_acc[idx[3 * e + 2]], payload);
            }
        }
        // scalar tail (nH % 4)
        int tailStart = nGroups << 2;
        int t = tailStart + g;
        if (t < nH && g < (nH - tailStart)) {
            int i0 = he[3 * t + 0];
            int i1 = he[3 * t + 1];
            int i2 = he[3 * t + 2];
            float p = 0.9f * __ldg(x + i1) * __ldg(x + i2);
            unsigned long long payload = pack_hyper(p);
            atomicAdd(&g_acc[i0], payload);
            atomicAdd(&g_acc[i1], payload);
            atomicAdd(&g_acc[i2], payload);
        }
    } else {
        // ---- adjacency edges: 8 edges per thread via 4x streaming int4 ----
        const int g = ((int)blockIdx.x - hyperBlocks) * blockDim.x + threadIdx.x;
        const int nGroups = nA >> 3;

        if (g < nGroups) {
            const int4* adj4 = (const int4*)adj;
            int4 e0 = __ldcs(adj4 + 4 * g + 0);  // (s0,d0,s1,d1)
            int4 e1 = __ldcs(adj4 + 4 * g + 1);
            int4 e2 = __ldcs(adj4 + 4 * g + 2);
            int4 e3 = __ldcs(adj4 + 4 * g + 3);
            int s[8] = { e0.x, e0.z, e1.x, e1.z, e2.x, e2.z, e3.x, e3.z };
            int d[8] = { e0.y, e0.w, e1.y, e1.w, e2.y, e2.w, e3.y, e3.w };
            float xs[8];
            #pragma unroll
            for (int k = 0; k < 8; k++) xs[k] = __ldg(x + s[k]);
            #pragma unroll
            for (int k = 0; k < 8; k++)
                atomicAdd(&g_acc[d[k]], pack_adj(0.1f * xs[k]));
        }
        // scalar tail (nA % 8)
        int tailStart = nGroups << 3;
        int t = tailStart + g;
        if (t < nA && g < (nA - tailStart)) {
            int s = adj[2 * t + 0];
            int d = adj[2 * t + 1];
            atomicAdd(&g_acc[d], pack_adj(0.1f * __ldg(x + s)));
        }
    }
}

__global__ void decode_kernel(const float* __restrict__ x,
                              float*       __restrict__ out,
                              int N)
{
    int n2 = blockIdx.x * blockDim.x + threadIdx.x;   // pair of nodes
    int base = n2 * 2;
    if (base >= N) return;

    ulonglong2 av = *(ulonglong2*)(g_acc + base);
    // re-zero for the next graph replay (restores load-time-zero invariant)
    ulonglong2 z; z.x = 0ULL; z.y = 0ULL;
    *(ulonglong2*)(g_acc + base) = z;

    float2 xv2 = *(const float2*)(x + base);
    unsigned long long aa[2] = { av.x, av.y };
    float xs[2] = { xv2.x, xv2.y };
    float r[2];
    #pragma unroll
    for (int k = 0; k < 2; k++) {
        unsigned long long a = aa[k];
        double sum = (double)(a & ((1ULL << 40) - 1)) * (1.0 / (double)FX_SCALE);
        int cntH = (int)((a >> 40) & 0xFFF);
        int degA = (int)((a >> 52) & 0xFFF);
        float xv = xs[k];
        r[k] = (float)sum - 0.1f * (float)degA * xv - 0.9f * (float)cntH * xv * xv;
    }
    if (base + 1 < N) {
        *(float2*)(out + base) = make_float2(r[0], r[1]);
    } else {
        out[base] = r[0];
    }
}

extern "C" void kernel_launch(void* const* d_in, const int* in_sizes, int n_in,
                              void* d_out, int out_size)
{
    const float* x   = (const float*)d_in[0];
    const int*   he  = (const int*)d_in[2];
    const int*   adj = (const int*)d_in[3];
    float*       out = (float*)d_out;

    const int nH = in_sizes[2] / 3;
    const int nA = in_sizes[3] / 2;
    const int N  = out_size;

    const int threads = 256;

    int hyperBlocks = ((nH >> 2) + threads - 1) / threads;
    if (hyperBlocks < 1) hyperBlocks = 1;
    int adjBlocks = ((nA >> 3) + threads - 1) / threads;
    if (adjBlocks < 1) adjBlocks = 1;

    edge_kernel<<<hyperBlocks + adjBlocks, threads>>>(x, he, nH, adj, nA,
                                                      hyperBlocks);

    int decBlocks = ((N + 1) / 2 + threads - 1) / threads;
    decode_kernel<<<decBlocks, threads>>>(x, out, N);
}

// round 13
// speedup vs baseline: 1.1142x; 1.0322x over previous
#include <cuda_runtime.h>
#include <cuda_bf16.h>
#include <cstdint>

// out[n] = 0.1*Ax[n] - 0.1*deg[n]*x[n] + 0.9*(S[n] - cnt[n]*x[n]^2)
//
// Bound: shared LSU/L1tex lane-op throughput. Lane count is algebraically
// minimal: hyper edge = 2 gathers + 3 REDs, adj edge = 1 gather + 1 RED
// (57M lane-ops). Config below is the best-measured combination:
//   - hyper: 4 edges/thread (3x int4 streaming), batched gathers
//   - adj:   4 edges/thread (2x int4 streaming)
//   - no quant pass (f32 gathers; hit-rate doesn't matter, only lane count)
//   - no memset node (decode re-zeros g_acc, preserving load-time zero)
//   - all-float decode (no fp64)
//
// Per-node 64-bit packed accumulator, one RED.E.ADD.U64 per edge slot:
//   bits [ 0:40) fixed-point sum of (0.1*x[src]) and (0.9*p), scale 2^30
//   bits [40:52) hyper slot count
//   bits [52:64) adjacency degree

#define MAX_N    524288
#define FX_SCALE 1073741824.0f   // 2^30

__device__ unsigned long long g_acc[MAX_N];   // zero-initialized at load

__device__ __forceinline__ unsigned long long pack_hyper(float v) {
    return (1ULL << 40) | (unsigned long long)__float2uint_rn(v * FX_SCALE);
}
__device__ __forceinline__ unsigned long long pack_adj(float v) {
    return (1ULL << 52) | (unsigned long long)__float2uint_rn(v * FX_SCALE);
}

__global__ void edge_kernel(const float* __restrict__ x,
                            const int*   __restrict__ he,   // [nH*3]
                            int nH,
                            const int*   __restrict__ adj,  // [nA*2]
                            int nA,
                            int hyperBlocks)
{
    if ((int)blockIdx.x < hyperBlocks) {
        // ---- hyper edges: 4 edges (12 ints) per thread via 3x streaming int4 ----
        const int g = blockIdx.x * blockDim.x + threadIdx.x;
        const int nGroups = nH >> 2;

        if (g < nGroups) {
            const int4* he4 = (const int4*)he;
            int4 a = __ldcs(he4 + 3 * g + 0);
            int4 b = __ldcs(he4 + 3 * g + 1);
            int4 c = __ldcs(he4 + 3 * g + 2);
            int idx[12] = { a.x, a.y, a.z, a.w,
                            b.x, b.y, b.z, b.w,
                            c.x, c.y, c.z, c.w };
            float xv[8];
            #pragma unroll
            for (int e = 0; e < 4; e++) {
                xv[2 * e + 0] = __ldg(x + idx[3 * e + 1]);
                xv[2 * e + 1] = __ldg(x + idx[3 * e + 2]);
            }
            #pragma unroll
            for (int e = 0; e < 4; e++) {
                float p = 0.9f * xv[2 * e + 0] * xv[2 * e + 1];
                unsigned long long payload = pack_hyper(p);
                atomicAdd(&g_acc[idx[3 * e + 0]], payload);
                atomicAdd(&g_acc[idx[3 * e + 1]], payload);
                atomicAdd(&g_acc[idx[3 * e + 2]], payload);
            }
        }
        // scalar tail (nH % 4)
        int tailStart = nGroups << 2;
        int t = tailStart + g;
        if (t < nH && g < (nH - tailStart)) {
            int i0 = he[3 * t + 0];
            int i1 = he[3 * t + 1];
            int i2 = he[3 * t + 2];
            float p = 0.9f * __ldg(x + i1) * __ldg(x + i2);
            unsigned long long payload = pack_hyper(p);
            atomicAdd(&g_acc[i0], payload);
            atomicAdd(&g_acc[i1], payload);
            atomicAdd(&g_acc[i2], payload);
        }
    } else {
        // ---- adjacency edges: 4 edges per thread via 2x streaming int4 ----
        const int g = ((int)blockIdx.x - hyperBlocks) * blockDim.x + threadIdx.x;
        const int nGroups = nA >> 2;

        if (g < nGroups) {
            const int4* adj4 = (const int4*)adj;
            int4 e0 = __ldcs(adj4 + 2 * g + 0);  // (s0,d0,s1,d1)
            int4 e1 = __ldcs(adj4 + 2 * g + 1);  // (s2,d2,s3,d3)
            float s0 = __ldg(x + e0.x);
            float s1 = __ldg(x + e0.z);
            float s2 = __ldg(x + e1.x);
            float s3 = __ldg(x + e1.z);
            atomicAdd(&g_acc[e0.y], pack_adj(0.1f * s0));
            atomicAdd(&g_acc[e0.w], pack_adj(0.1f * s1));
            atomicAdd(&g_acc[e1.y], pack_adj(0.1f * s2));
            atomicAdd(&g_acc[e1.w], pack_adj(0.1f * s3));
        }
        // scalar tail (nA % 4)
        int tailStart = nGroups << 2;
        int t = tailStart + g;
        if (t < nA && g < (nA - tailStart)) {
            int s = adj[2 * t + 0];
            int d = adj[2 * t + 1];
            atomicAdd(&g_acc[d], pack_adj(0.1f * __ldg(x + s)));
        }
    }
}

__global__ void decode_kernel(const float* __restrict__ x,
                              float*       __restrict__ out,
                              int N)
{
    int n2 = blockIdx.x * blockDim.x + threadIdx.x;   // pair of nodes
    int base = n2 * 2;
    if (base >= N) return;

    ulonglong2 av = *(ulonglong2*)(g_acc + base);
    // re-zero for the next graph replay (restores load-time-zero invariant)
    ulonglong2 z; z.x = 0ULL; z.y = 0ULL;
    *(ulonglong2*)(g_acc + base) = z;

    float2 xv2 = *(const float2*)(x + base);
    unsigned long long aa[2] = { av.x, av.y };
    float xs[2] = { xv2.x, xv2.y };
    float r[2];
    #pragma unroll
    for (int k = 0; k < 2; k++) {
        unsigned long long a = aa[k];
        // 40-bit sum -> float directly (max ~2^37; f32 rel err 6e-8 is ample)
        float sum = (float)(a & ((1ULL << 40) - 1)) * (1.0f / FX_SCALE);
        int cntH = (int)((a >> 40) & 0xFFF);
        int degA = (int)((a >> 52) & 0xFFF);
        float xv = xs[k];
        r[k] = sum - 0.1f * (float)degA * xv - 0.9f * (float)cntH * xv * xv;
    }
    if (base + 1 < N) {
        *(float2*)(out + base) = make_float2(r[0], r[1]);
    } else {
        out[base] = r[0];
    }
}

extern "C" void kernel_launch(void* const* d_in, const int* in_sizes, int n_in,
                              void* d_out, int out_size)
{
    const float* x   = (const float*)d_in[0];
    const int*   he  = (const int*)d_in[2];
    const int*   adj = (const int*)d_in[3];
    float*       out = (float*)d_out;

    const int nH = in_sizes[2] / 3;
    const int nA = in_sizes[3] / 2;
    const int N  = out_size;

    const int threads = 256;

    int hyperBlocks = ((nH >> 2) + threads - 1) / threads;
    if (hyperBlocks < 1) hyperBlocks = 1;
    int adjBlocks = ((nA >> 2) + threads - 1) / threads;
    if (adjBlocks < 1) adjBlocks = 1;

    edge_kernel<<<hyperBlocks + adjBlocks, threads>>>(x, he, nH, adj, nA,
                                                      hyperBlocks);

    int decBlocks = ((N + 1) / 2 + threads - 1) / threads;
    decode_kernel<<<decBlocks, threads>>>(x, out, N);
}